// round 2
// baseline (speedup 1.0000x reference)
#include <cuda_runtime.h>
#include <math.h>

#define NUM_USER 200000
#define NUM_ITEM 200000
#define DIM_E    64
#define DIM_F    128
#define HID      256
#define BATCH    16384
#define GRP      17
#define NTOT     (BATCH * GRP)   // 278528

#define RPB      32   // rows per block (encoder)
#define RI       8    // rows per inner iteration
#define W1T_LD   132  // padded lead dim for transposed W1 (conflict-free LDS.128 phases)
#define W2T_LD   260  // padded lead dim for transposed W2

// Scratch (static device globals: allocation-free per harness rules)
__device__ float         g_feature[(size_t)NUM_ITEM * DIM_E];  // 51.2 MB
__device__ unsigned char g_mask[NTOT];
__device__ float         g_accum[2];

// ---------------------------------------------------------------------------
// Prep: zero mask + accumulators
// ---------------------------------------------------------------------------
__global__ void zero_kernel() {
    int i = blockIdx.x * blockDim.x + threadIdx.x;
    if (i < NTOT / 4) ((unsigned int*)g_mask)[i] = 0u;
    if (i < 2) g_accum[i] = 0.0f;
}

// Scatter rand_index -> mask (duplicates write the same value: benign race)
__global__ void scatter_kernel(const int* __restrict__ rand_index, int n) {
    int i = blockIdx.x * blockDim.x + threadIdx.x;
    if (i < n) g_mask[rand_index[i]] = 1;
}

// ---------------------------------------------------------------------------
// Fused encoder: feature = leaky_relu(l2norm(v_feat) @ W1 + b1) @ W2 + b2
// One CTA = 32 rows. Weights live transposed in SMEM (loaded once per CTA).
// ---------------------------------------------------------------------------
__global__ void __launch_bounds__(256, 1) encoder_kernel(
    const float* __restrict__ v_feat,
    const float* __restrict__ W1, const float* __restrict__ b1,
    const float* __restrict__ W2, const float* __restrict__ b2)
{
    extern __shared__ float sm[];
    float* w1t = sm;                        // [HID][W1T_LD]   (transposed W1)
    float* w2t = w1t + HID * W1T_LD;        // [DIM_E][W2T_LD] (transposed W2)
    float* vfs = w2t + DIM_E * W2T_LD;      // [RI][DIM_F]     normalized input rows
    float* hbs = vfs + RI * DIM_F;          // [RI][HID]       hidden activations
    float* b1s = hbs + RI * HID;            // [HID]
    float* b2s = b1s + HID;                 // [DIM_E]

    const int tid = threadIdx.x;

    // Stage weights (coalesced global read, transposed smem write)
    for (int idx = tid; idx < DIM_F * HID; idx += 256) {
        int k = idx >> 8, j = idx & 255;
        w1t[j * W1T_LD + k] = W1[idx];
    }
    for (int idx = tid; idx < HID * DIM_E; idx += 256) {
        int j = idx >> 6, e = idx & 63;
        w2t[e * W2T_LD + j] = W2[idx];
    }
    if (tid < HID)   b1s[tid] = b1[tid];
    if (tid < DIM_E) b2s[tid] = b2[tid];
    __syncthreads();

    const int row0 = blockIdx.x * RPB;
    const int w    = tid >> 5;
    const int lane = tid & 31;

    for (int r0 = 0; r0 < RPB; r0 += RI) {
        // --- stage + l2-normalize RI rows (one warp per row) ---
        {
            int row = row0 + r0 + w;
            float4 v = ((const float4*)(v_feat + (size_t)row * DIM_F))[lane];
            float ss = v.x * v.x + v.y * v.y + v.z * v.z + v.w * v.w;
            #pragma unroll
            for (int o = 16; o; o >>= 1) ss += __shfl_xor_sync(0xffffffffu, ss, o);
            float inv = 1.0f / fmaxf(sqrtf(ss), 1e-12f);
            float4 vn = make_float4(v.x * inv, v.y * inv, v.z * inv, v.w * inv);
            ((float4*)(vfs + w * DIM_F))[lane] = vn;
        }
        __syncthreads();

        // --- phase 1: h[r][tid] = l2norm-row dot W1 column tid  ---
        float acc[RI];
        #pragma unroll
        for (int r = 0; r < RI; r++) acc[r] = b1s[tid];
        #pragma unroll 4
        for (int kc = 0; kc < DIM_F; kc += 4) {
            float4 wv = *(const float4*)(w1t + tid * W1T_LD + kc);
            #pragma unroll
            for (int r = 0; r < RI; r++) {
                float4 vv = *(const float4*)(vfs + r * DIM_F + kc);
                acc[r] = fmaf(wv.x, vv.x, acc[r]);
                acc[r] = fmaf(wv.y, vv.y, acc[r]);
                acc[r] = fmaf(wv.z, vv.z, acc[r]);
                acc[r] = fmaf(wv.w, vv.w, acc[r]);
            }
        }
        #pragma unroll
        for (int r = 0; r < RI; r++) {
            float h = acc[r];
            h = (h > 0.0f) ? h : 0.01f * h;   // leaky_relu, slope 0.01
            hbs[r * HID + tid] = h;
        }
        __syncthreads();

        // --- phase 2: feature[row][e] = h[row] dot W2 column e ---
        {
            int e  = tid & 63;
            int rr = tid >> 6;                 // 0..3, handles rows rr and rr+4
            float a0 = b2s[e], a1 = b2s[e];
            #pragma unroll 4
            for (int jc = 0; jc < HID; jc += 4) {
                float4 wv = *(const float4*)(w2t + e * W2T_LD + jc);
                float4 h0 = *(const float4*)(hbs + rr * HID + jc);
                float4 h1 = *(const float4*)(hbs + (rr + 4) * HID + jc);
                a0 = fmaf(wv.x, h0.x, a0); a0 = fmaf(wv.y, h0.y, a0);
                a0 = fmaf(wv.z, h0.z, a0); a0 = fmaf(wv.w, h0.w, a0);
                a1 = fmaf(wv.x, h1.x, a1); a1 = fmaf(wv.y, h1.y, a1);
                a1 = fmaf(wv.z, h1.z, a1); a1 = fmaf(wv.w, h1.w, a1);
            }
            g_feature[(size_t)(row0 + r0 + rr)     * DIM_E + e] = a0;
            g_feature[(size_t)(row0 + r0 + rr + 4) * DIM_E + e] = a1;
        }
        __syncthreads();
    }
}

// ---------------------------------------------------------------------------
// Loss: one warp per batch row (17 pairs). Lanes cover 64 dims as float2.
// ---------------------------------------------------------------------------
__global__ void __launch_bounds__(256) loss_kernel(
    const float* __restrict__ id_emb,
    const int*   __restrict__ user_t,
    const int*   __restrict__ item_t)
{
    __shared__ float bs[2];
    if (threadIdx.x == 0) { bs[0] = 0.0f; bs[1] = 0.0f; }
    __syncthreads();

    int warp = (blockIdx.x * blockDim.x + threadIdx.x) >> 5;
    int lane = threadIdx.x & 31;

    if (warp < BATCH) {
        int base = warp * GRP;
        int pit  = item_t[base];   // positive item embedding index (repeated per row)
        float2 pe = ((const float2*)(id_emb + (size_t)pit * DIM_E))[lane];
        float ps = fmaf(pe.x, pe.x, pe.y * pe.y);
        #pragma unroll
        for (int o = 16; o; o >>= 1) ps += __shfl_xor_sync(0xffffffffu, ps, o);
        float inv_p = 1.0f / fmaxf(sqrtf(ps), 1e-12f);

        float tot1 = 0.0f, tot2 = 0.0f, pos1 = 0.0f, pos2 = 0.0f;
        for (int g = 0; g < GRP; ++g) {
            int it = item_t[base + g];
            int u  = user_t[base + g];
            int item = it - NUM_USER;
            item = min(max(item, 0), NUM_ITEM - 1);

            float2 f  = ((const float2*)(g_feature + (size_t)item * DIM_E))[lane];
            float2 ue = ((const float2*)(id_emb + (size_t)u * DIM_E))[lane];
            float2 av;
            if (g_mask[base + g]) av = f;   // uniform per warp: no divergence
            else av = ((const float2*)(id_emb + (size_t)it * DIM_E))[lane];

            float fn = fmaf(f.x, f.x, f.y * f.y);
            float d1 = fmaf(pe.x, f.x, pe.y * f.y);
            float d2 = fmaf(ue.x, av.x, ue.y * av.y);
            #pragma unroll
            for (int o = 16; o; o >>= 1) {
                fn += __shfl_xor_sync(0xffffffffu, fn, o);
                d1 += __shfl_xor_sync(0xffffffffu, d1, o);
                d2 += __shfl_xor_sync(0xffffffffu, d2, o);
            }
            float inv_f = 1.0f / fmaxf(sqrtf(fn), 1e-12f);
            float s1 = expf(d1 * inv_p * inv_f * 5.0f);   // 1/TEMP = 5
            float s2 = expf(d2 * 5.0f);
            tot1 += s1; tot2 += s2;
            if (g == 0) { pos1 = s1; pos2 = s2; }
        }
        if (lane == 0) {
            atomicAdd(&bs[0], -logf(pos1 / (tot1 + 1e-8f) + 1e-8f));
            atomicAdd(&bs[1], -logf(pos2 / (tot2 + 1e-8f) + 1e-8f));
        }
    }
    __syncthreads();
    if (threadIdx.x == 0) {
        atomicAdd(&g_accum[0], bs[0]);
        atomicAdd(&g_accum[1], bs[1]);
    }
}

// ---------------------------------------------------------------------------
// Finalize: out = 0.5 * mean(l1) + 0.5 * mean(l2)
// ---------------------------------------------------------------------------
__global__ void finalize_kernel(float* __restrict__ out, int n) {
    float v = (g_accum[0] + g_accum[1]) * (0.5f / (float)BATCH);
    for (int i = threadIdx.x; i < n; i += blockDim.x) out[i] = v;
}

// ---------------------------------------------------------------------------
extern "C" void kernel_launch(void* const* d_in, const int* in_sizes, int n_in,
                              void* d_out, int out_size)
{
    const float* v_feat = (const float*)d_in[0];
    const float* id_emb = (const float*)d_in[1];
    const float* W1     = (const float*)d_in[2];
    const float* b1     = (const float*)d_in[3];
    const float* W2     = (const float*)d_in[4];
    const float* b2     = (const float*)d_in[5];
    const int*   user_t = (const int*)d_in[6];
    const int*   item_t = (const int*)d_in[7];
    const int*   rand_i = (const int*)d_in[8];
    const int    n_rand = in_sizes[8];
    float*       out    = (float*)d_out;

    const size_t smem = (size_t)(HID * W1T_LD + DIM_E * W2T_LD +
                                 RI * DIM_F + RI * HID + HID + DIM_E) * sizeof(float);
    cudaFuncSetAttribute(encoder_kernel,
                         cudaFuncAttributeMaxDynamicSharedMemorySize, (int)smem);

    zero_kernel<<<(NTOT / 4 + 255) / 256, 256>>>();
    scatter_kernel<<<(n_rand + 255) / 256, 256>>>(rand_i, n_rand);
    encoder_kernel<<<NUM_ITEM / RPB, 256, smem>>>(v_feat, W1, b1, W2, b2);
    loss_kernel<<<BATCH / 8, 256>>>(id_emb, user_t, item_t);
    finalize_kernel<<<1, 32>>>(out, out_size > 0 ? out_size : 1);
}

// round 3
// speedup vs baseline: 3.4975x; 3.4975x over previous
#include <cuda_runtime.h>
#include <math.h>
#include <stdint.h>

#define NUM_USER 200000
#define NUM_ITEM 200000
#define DIM_E    64
#define DIM_F    128
#define HID      256
#define BATCH    16384
#define GRP      17
#define NTOT     (BATCH * GRP)   // 278528

#define MTILE    64              // rows per CTA (encoder)
#define AS_LD    132             // As stride:  132 % 32 == 4  -> conflict-free A frags
#define HS_LD    260             // Hs stride:  260 % 32 == 4  -> conflict-free A frags
#define W1_LD    264             // W1 chunk:   264 % 32 == 8  -> conflict-free B frags
#define W2_LD    72              // W2 chunk:    72 % 32 == 8  -> conflict-free B frags

#define AS_FL    (MTILE * AS_LD)          // 8448
#define HS_FL    (MTILE * HS_LD)          // 16640
#define WB_FL    (32 * W1_LD)             // 8448 (one buffer; W2 chunk 64*72=4608 fits)
#define SMEM_FL  (AS_FL + HS_FL + 2 * WB_FL + HID + DIM_E)

// Scratch (static device globals: allocation-free per harness rules)
__device__ float         g_feature[(size_t)NUM_ITEM * DIM_E];  // 51.2 MB
__device__ unsigned char g_mask[NTOT];
__device__ float         g_accum[2];

// ---------------------------------------------------------------------------
__device__ __forceinline__ uint32_t f2tf(float x) {
    uint32_t r;
    asm("cvt.rna.tf32.f32 %0, %1;" : "=r"(r) : "f"(x));
    return r;
}

__device__ __forceinline__ void mma_tf32(float* c, const uint32_t* a,
                                         uint32_t b0, uint32_t b1) {
    asm volatile(
        "mma.sync.aligned.m16n8k8.row.col.f32.tf32.tf32.f32 "
        "{%0,%1,%2,%3},{%4,%5,%6,%7},{%8,%9},{%0,%1,%2,%3};"
        : "+f"(c[0]), "+f"(c[1]), "+f"(c[2]), "+f"(c[3])
        : "r"(a[0]), "r"(a[1]), "r"(a[2]), "r"(a[3]), "r"(b0), "r"(b1));
}

__device__ __forceinline__ void cp_async16(void* dst, const void* src) {
    uint32_t s = (uint32_t)__cvta_generic_to_shared(dst);
    asm volatile("cp.async.ca.shared.global [%0], [%1], 16;" :: "r"(s), "l"(src));
}
__device__ __forceinline__ void cp_commit() {
    asm volatile("cp.async.commit_group;");
}
template <int N> __device__ __forceinline__ void cp_wait() {
    asm volatile("cp.async.wait_group %0;" :: "n"(N));
}

// ---------------------------------------------------------------------------
__global__ void zero_kernel() {
    int i = blockIdx.x * blockDim.x + threadIdx.x;
    if (i < NTOT / 4) ((unsigned int*)g_mask)[i] = 0u;
    if (i < 2) g_accum[i] = 0.0f;
}

__global__ void scatter_kernel(const int* __restrict__ rand_index, int n) {
    int i = blockIdx.x * blockDim.x + threadIdx.x;
    if (i < n) g_mask[rand_index[i]] = 1;
}

// ---------------------------------------------------------------------------
// TF32 tensor-core encoder. CTA = 64 rows. 8 warps.
// Layer1 (64x256x128): warps 2(m) x 4(n), warp tile 32x64.
// Layer2 (64x 64x256): warps 2(m) x 4(n), warp tile 32x16.
// Weights streamed in double-buffered cp.async chunks.
// ---------------------------------------------------------------------------
__global__ void __launch_bounds__(256, 1) encoder_kernel(
    const float* __restrict__ v_feat,
    const float* __restrict__ W1, const float* __restrict__ b1,
    const float* __restrict__ W2, const float* __restrict__ b2)
{
    extern __shared__ float sm[];
    float* As  = sm;                    // [64][AS_LD] normalized rows (tf32 bits)
    float* Hs  = As + AS_FL;            // [64][HS_LD] hidden (tf32 bits)
    float* Wb0 = Hs + HS_FL;            // weight chunk buffer 0
    float* Wb1 = Wb0 + WB_FL;           // weight chunk buffer 1
    float* b1s = Wb1 + WB_FL;           // [256]
    float* b2s = b1s + HID;             // [64]
    float* Wb[2] = {Wb0, Wb1};

    const int tid  = threadIdx.x;
    const int lane = tid & 31;
    const int warp = tid >> 5;
    const int g    = lane >> 2;     // groupID   (0..7)
    const int t    = lane & 3;      // thread-in-group (0..3)
    const int row0 = blockIdx.x * MTILE;

    // ---- issue W1 chunk 0 and 1 (k rows 0..31, 32..63) ----
    #pragma unroll
    for (int cb = 0; cb < 2; cb++) {
        for (int i = tid; i < 32 * 64; i += 256) {     // 32 rows x 64 x 16B
            int kr = i >> 6, seg = i & 63;
            cp_async16(Wb[cb] + kr * W1_LD + seg * 4,
                       W1 + (size_t)(cb * 32 + kr) * HID + seg * 4);
        }
        cp_commit();
    }

    // ---- biases ----
    if (tid < HID)   b1s[tid] = b1[tid];
    if (tid < DIM_E) b2s[tid] = b2[tid];

    // ---- stage + l2-normalize 64 rows into As (tf32-rounded) ----
    for (int i = 0; i < 8; i++) {
        int r = warp * 8 + i;
        float4 v = ((const float4*)(v_feat + (size_t)(row0 + r) * DIM_F))[lane];
        float ss = v.x * v.x + v.y * v.y + v.z * v.z + v.w * v.w;
        #pragma unroll
        for (int o = 16; o; o >>= 1) ss += __shfl_xor_sync(0xffffffffu, ss, o);
        float inv = 1.0f / fmaxf(sqrtf(ss), 1e-12f);
        float4 vn;
        vn.x = __uint_as_float(f2tf(v.x * inv));
        vn.y = __uint_as_float(f2tf(v.y * inv));
        vn.z = __uint_as_float(f2tf(v.z * inv));
        vn.w = __uint_as_float(f2tf(v.w * inv));
        *(float4*)(As + r * AS_LD + lane * 4) = vn;
    }

    // ================= layer 1 =================
    const int mrow  = (warp >> 2) * 32;
    const int nbase = (warp & 3) * 64;
    float acc1[2][8][4];
    #pragma unroll
    for (int mt = 0; mt < 2; mt++)
        #pragma unroll
        for (int nt = 0; nt < 8; nt++)
            #pragma unroll
            for (int q = 0; q < 4; q++) acc1[mt][nt][q] = 0.0f;

    #pragma unroll 1
    for (int c = 0; c < 4; c++) {
        cp_wait<1>();
        __syncthreads();
        const float* wb = Wb[c & 1];
        const int kbase = c * 32;
        #pragma unroll
        for (int ks = 0; ks < 4; ks++) {
            const int kA = kbase + ks * 8;
            const int kW = ks * 8;
            uint32_t a[2][4];
            #pragma unroll
            for (int mt = 0; mt < 2; mt++) {
                int r = mrow + mt * 16 + g;
                a[mt][0] = __float_as_uint(As[r * AS_LD + kA + t]);
                a[mt][1] = __float_as_uint(As[(r + 8) * AS_LD + kA + t]);
                a[mt][2] = __float_as_uint(As[r * AS_LD + kA + t + 4]);
                a[mt][3] = __float_as_uint(As[(r + 8) * AS_LD + kA + t + 4]);
            }
            #pragma unroll
            for (int nt = 0; nt < 8; nt++) {
                int col = nbase + nt * 8 + g;
                uint32_t b0 = f2tf(wb[(kW + t) * W1_LD + col]);
                uint32_t b1v = f2tf(wb[(kW + t + 4) * W1_LD + col]);
                mma_tf32(acc1[0][nt], a[0], b0, b1v);
                mma_tf32(acc1[1][nt], a[1], b0, b1v);
            }
        }
        __syncthreads();
        // prefetch: W1 chunks 2,3 then W2 chunks 0,1 into the freed buffer
        if (c < 2) {
            for (int i = tid; i < 32 * 64; i += 256) {
                int kr = i >> 6, seg = i & 63;
                cp_async16(Wb[c & 1] + kr * W1_LD + seg * 4,
                           W1 + (size_t)((c + 2) * 32 + kr) * HID + seg * 4);
            }
        } else {
            for (int i = tid; i < 64 * 16; i += 256) {   // 64 k-rows x 16 x 16B
                int kr = i >> 4, seg = i & 15;
                cp_async16(Wb[c & 1] + kr * W2_LD + seg * 4,
                           W2 + (size_t)((c - 2) * 64 + kr) * DIM_E + seg * 4);
            }
        }
        cp_commit();

        if (c == 3) {
            // epilogue 1: bias + leaky_relu -> Hs (tf32-rounded)
            #pragma unroll
            for (int mt = 0; mt < 2; mt++) {
                #pragma unroll
                for (int nt = 0; nt < 8; nt++) {
                    int r   = mrow + mt * 16 + g;
                    int col = nbase + nt * 8 + 2 * t;
                    float x0 = acc1[mt][nt][0] + b1s[col];
                    float x1 = acc1[mt][nt][1] + b1s[col + 1];
                    float x2 = acc1[mt][nt][2] + b1s[col];
                    float x3 = acc1[mt][nt][3] + b1s[col + 1];
                    x0 = (x0 > 0.0f) ? x0 : 0.01f * x0;
                    x1 = (x1 > 0.0f) ? x1 : 0.01f * x1;
                    x2 = (x2 > 0.0f) ? x2 : 0.01f * x2;
                    x3 = (x3 > 0.0f) ? x3 : 0.01f * x3;
                    float2 lo = make_float2(__uint_as_float(f2tf(x0)),
                                            __uint_as_float(f2tf(x1)));
                    float2 hi = make_float2(__uint_as_float(f2tf(x2)),
                                            __uint_as_float(f2tf(x3)));
                    *(float2*)(Hs + r * HS_LD + col)       = lo;
                    *(float2*)(Hs + (r + 8) * HS_LD + col) = hi;
                }
            }
        }
    }

    // ================= layer 2 =================
    const int n2base = (warp & 3) * 16;
    float acc2[2][2][4];
    #pragma unroll
    for (int mt = 0; mt < 2; mt++)
        #pragma unroll
        for (int nt = 0; nt < 2; nt++)
            #pragma unroll
            for (int q = 0; q < 4; q++) acc2[mt][nt][q] = 0.0f;

    #pragma unroll 1
    for (int c = 0; c < 4; c++) {
        cp_wait<1>();
        __syncthreads();
        const float* wb = Wb[c & 1];
        const int kbase = c * 64;
        #pragma unroll
        for (int ks = 0; ks < 8; ks++) {
            const int kA = kbase + ks * 8;
            const int kW = ks * 8;
            uint32_t a[2][4];
            #pragma unroll
            for (int mt = 0; mt < 2; mt++) {
                int r = mrow + mt * 16 + g;
                a[mt][0] = __float_as_uint(Hs[r * HS_LD + kA + t]);
                a[mt][1] = __float_as_uint(Hs[(r + 8) * HS_LD + kA + t]);
                a[mt][2] = __float_as_uint(Hs[r * HS_LD + kA + t + 4]);
                a[mt][3] = __float_as_uint(Hs[(r + 8) * HS_LD + kA + t + 4]);
            }
            #pragma unroll
            for (int nt = 0; nt < 2; nt++) {
                int col = n2base + nt * 8 + g;
                uint32_t b0 = f2tf(wb[(kW + t) * W2_LD + col]);
                uint32_t b1v = f2tf(wb[(kW + t + 4) * W2_LD + col]);
                mma_tf32(acc2[0][nt], a[0], b0, b1v);
                mma_tf32(acc2[1][nt], a[1], b0, b1v);
            }
        }
        __syncthreads();
        if (c < 2) {   // prefetch W2 chunks 2,3
            for (int i = tid; i < 64 * 16; i += 256) {
                int kr = i >> 4, seg = i & 15;
                cp_async16(Wb[c & 1] + kr * W2_LD + seg * 4,
                           W2 + (size_t)((c + 2) * 64 + kr) * DIM_E + seg * 4);
            }
        }
        cp_commit();
    }

    // epilogue 2: + b2 -> g_feature
    #pragma unroll
    for (int mt = 0; mt < 2; mt++) {
        #pragma unroll
        for (int nt = 0; nt < 2; nt++) {
            int r   = row0 + mrow + mt * 16 + g;
            int col = n2base + nt * 8 + 2 * t;
            float2 lo = make_float2(acc2[mt][nt][0] + b2s[col],
                                    acc2[mt][nt][1] + b2s[col + 1]);
            float2 hi = make_float2(acc2[mt][nt][2] + b2s[col],
                                    acc2[mt][nt][3] + b2s[col + 1]);
            *(float2*)(g_feature + (size_t)r * DIM_E + col)       = lo;
            *(float2*)(g_feature + (size_t)(r + 8) * DIM_E + col) = hi;
        }
    }
}

// ---------------------------------------------------------------------------
// Loss: one warp per batch row (17 pairs). Lanes cover 64 dims as float2.
// ---------------------------------------------------------------------------
__global__ void __launch_bounds__(256) loss_kernel(
    const float* __restrict__ id_emb,
    const int*   __restrict__ user_t,
    const int*   __restrict__ item_t)
{
    __shared__ float bs[2];
    if (threadIdx.x == 0) { bs[0] = 0.0f; bs[1] = 0.0f; }
    __syncthreads();

    int warp = (blockIdx.x * blockDim.x + threadIdx.x) >> 5;
    int lane = threadIdx.x & 31;

    if (warp < BATCH) {
        int base = warp * GRP;
        int pit  = item_t[base];
        float2 pe = ((const float2*)(id_emb + (size_t)pit * DIM_E))[lane];
        float ps = fmaf(pe.x, pe.x, pe.y * pe.y);
        #pragma unroll
        for (int o = 16; o; o >>= 1) ps += __shfl_xor_sync(0xffffffffu, ps, o);
        float inv_p = 1.0f / fmaxf(sqrtf(ps), 1e-12f);

        float tot1 = 0.0f, tot2 = 0.0f, pos1 = 0.0f, pos2 = 0.0f;
        for (int gi = 0; gi < GRP; ++gi) {
            int it = item_t[base + gi];
            int u  = user_t[base + gi];
            int item = it - NUM_USER;
            item = min(max(item, 0), NUM_ITEM - 1);

            float2 f  = ((const float2*)(g_feature + (size_t)item * DIM_E))[lane];
            float2 ue = ((const float2*)(id_emb + (size_t)u * DIM_E))[lane];
            float2 av;
            if (g_mask[base + gi]) av = f;
            else av = ((const float2*)(id_emb + (size_t)it * DIM_E))[lane];

            float fn = fmaf(f.x, f.x, f.y * f.y);
            float d1 = fmaf(pe.x, f.x, pe.y * f.y);
            float d2 = fmaf(ue.x, av.x, ue.y * av.y);
            #pragma unroll
            for (int o = 16; o; o >>= 1) {
                fn += __shfl_xor_sync(0xffffffffu, fn, o);
                d1 += __shfl_xor_sync(0xffffffffu, d1, o);
                d2 += __shfl_xor_sync(0xffffffffu, d2, o);
            }
            float inv_f = 1.0f / fmaxf(sqrtf(fn), 1e-12f);
            float s1 = expf(d1 * inv_p * inv_f * 5.0f);
            float s2 = expf(d2 * 5.0f);
            tot1 += s1; tot2 += s2;
            if (gi == 0) { pos1 = s1; pos2 = s2; }
        }
        if (lane == 0) {
            atomicAdd(&bs[0], -logf(pos1 / (tot1 + 1e-8f) + 1e-8f));
            atomicAdd(&bs[1], -logf(pos2 / (tot2 + 1e-8f) + 1e-8f));
        }
    }
    __syncthreads();
    if (threadIdx.x == 0) {
        atomicAdd(&g_accum[0], bs[0]);
        atomicAdd(&g_accum[1], bs[1]);
    }
}

// ---------------------------------------------------------------------------
__global__ void finalize_kernel(float* __restrict__ out, int n) {
    float v = (g_accum[0] + g_accum[1]) * (0.5f / (float)BATCH);
    for (int i = threadIdx.x; i < n; i += blockDim.x) out[i] = v;
}

// ---------------------------------------------------------------------------
extern "C" void kernel_launch(void* const* d_in, const int* in_sizes, int n_in,
                              void* d_out, int out_size)
{
    const float* v_feat = (const float*)d_in[0];
    const float* id_emb = (const float*)d_in[1];
    const float* W1     = (const float*)d_in[2];
    const float* b1     = (const float*)d_in[3];
    const float* W2     = (const float*)d_in[4];
    const float* b2     = (const float*)d_in[5];
    const int*   user_t = (const int*)d_in[6];
    const int*   item_t = (const int*)d_in[7];
    const int*   rand_i = (const int*)d_in[8];
    const int    n_rand = in_sizes[8];
    float*       out    = (float*)d_out;

    const size_t smem = (size_t)SMEM_FL * sizeof(float);   // ~169 KB
    cudaFuncSetAttribute(encoder_kernel,
                         cudaFuncAttributeMaxDynamicSharedMemorySize, (int)smem);

    zero_kernel<<<(NTOT / 4 + 255) / 256, 256>>>();
    scatter_kernel<<<(n_rand + 255) / 256, 256>>>(rand_i, n_rand);
    encoder_kernel<<<NUM_ITEM / MTILE, 256, smem>>>(v_feat, W1, b1, W2, b2);
    loss_kernel<<<BATCH / 8, 256>>>(id_emb, user_t, item_t);
    finalize_kernel<<<1, 32>>>(out, out_size > 0 ? out_size : 1);
}

// round 8
// speedup vs baseline: 6.7758x; 1.9373x over previous
#include <cuda_runtime.h>
#include <cuda_bf16.h>
#include <math.h>
#include <stdint.h>

#define NUM_USER 200000
#define NUM_ITEM 200000
#define DIM_E    64
#define DIM_F    128
#define HID      256
#define BATCH    16384
#define GRP      17
#define NTOT     (BATCH * GRP)   // 278528

#define MTILE    128
#define THREADS  512
#define AS_LDW   68    // As pitch in 32-bit words (64 data + 4 pad), 68%32==4
#define HS_LDW   132   // Hs pitch (128 data + 4 pad), 132%32==4
#define W1_LDW   68    // packed W1 pitch per col (64 data + 4 pad)
#define W2_LDW   132   // packed W2 pitch per col (128 data + 4 pad)

#define WP1_WORDS (HID * W1_LDW)      // 17408
#define WP2_WORDS (DIM_E * W2_LDW)    //  8448
#define AS_WORDS  (MTILE * AS_LDW)    //  8704
#define HS_WORDS  (MTILE * HS_LDW)    // 16896
#define SMEM_WORDS (WP1_WORDS + WP2_WORDS + AS_WORDS + HS_WORDS + HID + DIM_E)

// Scratch (static device globals: allocation-free per harness rules)
__device__ float         g_feature[(size_t)NUM_ITEM * DIM_E];  // 51.2 MB
__device__ unsigned int  g_wp1[WP1_WORDS];
__device__ unsigned int  g_wp2[WP2_WORDS];
__device__ unsigned char g_mask[NTOT];
__device__ float         g_accum[2];

// ---------------------------------------------------------------------------
__device__ __forceinline__ uint32_t pk_bf16x2(float lo, float hi) {
    __nv_bfloat162 h = __floats2bfloat162_rn(lo, hi);   // .x = lo (low half)
    return *reinterpret_cast<uint32_t*>(&h);
}

__device__ __forceinline__ void mma_bf16(float* c, const uint32_t* a,
                                         uint32_t b0, uint32_t b1) {
    asm volatile(
        "mma.sync.aligned.m16n8k16.row.col.f32.bf16.bf16.f32 "
        "{%0,%1,%2,%3},{%4,%5,%6,%7},{%8,%9},{%0,%1,%2,%3};"
        : "+f"(c[0]), "+f"(c[1]), "+f"(c[2]), "+f"(c[3])
        : "r"(a[0]), "r"(a[1]), "r"(a[2]), "r"(a[3]), "r"(b0), "r"(b1));
}

__device__ __forceinline__ void ldsm_x4(uint32_t* a, const uint32_t* p) {
    uint32_t s = (uint32_t)__cvta_generic_to_shared(p);
    asm volatile("ldmatrix.sync.aligned.m8n8.x4.shared.b16 {%0,%1,%2,%3},[%4];"
                 : "=r"(a[0]), "=r"(a[1]), "=r"(a[2]), "=r"(a[3]) : "r"(s));
}

__device__ __forceinline__ void cp_async16(void* dst, const void* src) {
    uint32_t s = (uint32_t)__cvta_generic_to_shared(dst);
    asm volatile("cp.async.ca.shared.global [%0], [%1], 16;" :: "r"(s), "l"(src));
}
__device__ __forceinline__ void cp_commit() { asm volatile("cp.async.commit_group;"); }
__device__ __forceinline__ void cp_wait0()  { asm volatile("cp.async.wait_group 0;"); }

// ---------------------------------------------------------------------------
__global__ void zero_kernel() {
    int i = blockIdx.x * blockDim.x + threadIdx.x;
    if (i < NTOT / 4) ((unsigned int*)g_mask)[i] = 0u;
    if (i < 2) g_accum[i] = 0.0f;
}

__global__ void scatter_kernel(const int* __restrict__ rand_index, int n) {
    int i = blockIdx.x * blockDim.x + threadIdx.x;
    if (i < n) g_mask[rand_index[i]] = 1;
}

// Pack weights into bf16x2 B-fragment layout (col-major, padded pitch).
__global__ void pack_kernel(const float* __restrict__ W1,
                            const float* __restrict__ W2) {
    int i = blockIdx.x * blockDim.x + threadIdx.x;
    if (i < WP1_WORDS) {
        int col = i / W1_LDW, w = i % W1_LDW;
        unsigned int v = 0u;
        if (w < DIM_F / 2)
            v = pk_bf16x2(W1[(size_t)(2 * w) * HID + col],
                          W1[(size_t)(2 * w + 1) * HID + col]);
        g_wp1[i] = v;
    }
    int j = i - WP1_WORDS;
    if (j >= 0 && j < WP2_WORDS) {
        int col = j / W2_LDW, w = j % W2_LDW;
        unsigned int v = 0u;
        if (w < HID / 2)
            v = pk_bf16x2(W2[(size_t)(2 * w) * DIM_E + col],
                          W2[(size_t)(2 * w + 1) * DIM_E + col]);
        g_wp2[j] = v;
    }
}

// ---------------------------------------------------------------------------
// BF16 tensor-core encoder. CTA = 128 rows, 16 warps.
// Layer1 (128x256x128): warps 4m x 4n, warp tile 32x64.
// Layer2 (128x 64x256): warps 4m x 4n, warp tile 32x16.
// ---------------------------------------------------------------------------
__global__ void __launch_bounds__(THREADS, 1) encoder_kernel(
    const float* __restrict__ v_feat,
    const float* __restrict__ b1, const float* __restrict__ b2)
{
    extern __shared__ uint32_t smu[];
    uint32_t* Wp1s = smu;                       // [256][W1_LDW]
    uint32_t* Wp2s = Wp1s + WP1_WORDS;          // [ 64][W2_LDW]
    uint32_t* As   = Wp2s + WP2_WORDS;          // [128][AS_LDW]
    uint32_t* Hs   = As + AS_WORDS;             // [128][HS_LDW]
    float*    b1s  = (float*)(Hs + HS_WORDS);   // [256]
    float*    b2s  = b1s + HID;                 // [64]

    const int tid  = threadIdx.x;
    const int lane = tid & 31;
    const int warp = tid >> 5;
    const int g    = lane >> 2;       // 0..7
    const int t    = lane & 3;        // 0..3
    const int lrow = lane & 7;        // ldmatrix row-in-tile
    const int lsel = lane >> 3;       // ldmatrix matrix select 0..3
    const int row0 = blockIdx.x * MTILE;

    // ---- stream all packed weights into SMEM (linear cp.async) ----
    for (int i = tid; i < WP1_WORDS / 4; i += THREADS)
        cp_async16(Wp1s + i * 4, g_wp1 + i * 4);
    for (int i = tid; i < WP2_WORDS / 4; i += THREADS)
        cp_async16(Wp2s + i * 4, g_wp2 + i * 4);
    cp_commit();

    if (tid < HID)   b1s[tid] = b1[tid];
    if (tid < DIM_E) b2s[tid] = b2[tid];

    // ---- stage + l2-normalize 128 rows into As as bf16x2 ----
    #pragma unroll
    for (int i = 0; i < 8; i++) {
        int r = warp * 8 + i;
        int grow = row0 + r;
        int gc = min(grow, NUM_ITEM - 1);
        float4 v = ((const float4*)(v_feat + (size_t)gc * DIM_F))[lane];
        float ss = v.x * v.x + v.y * v.y + v.z * v.z + v.w * v.w;
        #pragma unroll
        for (int o = 16; o; o >>= 1) ss += __shfl_xor_sync(0xffffffffu, ss, o);
        float inv = 1.0f / fmaxf(sqrtf(ss), 1e-12f);
        uint2 w2;
        w2.x = pk_bf16x2(v.x * inv, v.y * inv);
        w2.y = pk_bf16x2(v.z * inv, v.w * inv);
        *(uint2*)(As + r * AS_LDW + lane * 2) = w2;
    }

    cp_wait0();
    __syncthreads();

    // ================= layer 1 =================
    const int mrow  = (warp >> 2) * 32;
    const int nbase = (warp & 3) * 64;
    float acc1[2][8][4];
    #pragma unroll
    for (int mt = 0; mt < 2; mt++)
        #pragma unroll
        for (int nt = 0; nt < 8; nt++)
            #pragma unroll
            for (int q = 0; q < 4; q++) acc1[mt][nt][q] = 0.0f;

    #pragma unroll
    for (int ks = 0; ks < DIM_F / 16; ks++) {        // 8 k-steps of 16
        uint32_t a[2][4];
        #pragma unroll
        for (int mt = 0; mt < 2; mt++)
            ldsm_x4(a[mt], As + (mrow + mt * 16 + lrow + (lsel & 1) * 8) * AS_LDW
                              + ks * 8 + (lsel >> 1) * 4);
        #pragma unroll
        for (int nt = 0; nt < 8; nt++) {
            int col = nbase + nt * 8 + g;
            uint32_t b0 = Wp1s[col * W1_LDW + ks * 8 + t];
            uint32_t bv = Wp1s[col * W1_LDW + ks * 8 + t + 4];
            mma_bf16(acc1[0][nt], a[0], b0, bv);
            mma_bf16(acc1[1][nt], a[1], b0, bv);
        }
    }

    // epilogue 1: bias + leaky_relu -> Hs (bf16x2)
    #pragma unroll
    for (int mt = 0; mt < 2; mt++) {
        #pragma unroll
        for (int nt = 0; nt < 8; nt++) {
            int r   = mrow + mt * 16 + g;
            int col = nbase + nt * 8 + 2 * t;
            float x0 = acc1[mt][nt][0] + b1s[col];
            float x1 = acc1[mt][nt][1] + b1s[col + 1];
            float x2 = acc1[mt][nt][2] + b1s[col];
            float x3 = acc1[mt][nt][3] + b1s[col + 1];
            x0 = (x0 > 0.0f) ? x0 : 0.01f * x0;
            x1 = (x1 > 0.0f) ? x1 : 0.01f * x1;
            x2 = (x2 > 0.0f) ? x2 : 0.01f * x2;
            x3 = (x3 > 0.0f) ? x3 : 0.01f * x3;
            int wofs = (nbase >> 1) + nt * 4 + t;
            Hs[r * HS_LDW + wofs]       = pk_bf16x2(x0, x1);
            Hs[(r + 8) * HS_LDW + wofs] = pk_bf16x2(x2, x3);
        }
    }
    __syncthreads();

    // ================= layer 2 =================
    const int nb2 = (warp & 3) * 16;
    float acc2[2][2][4];
    #pragma unroll
    for (int mt = 0; mt < 2; mt++)
        #pragma unroll
        for (int nt = 0; nt < 2; nt++)
            #pragma unroll
            for (int q = 0; q < 4; q++) acc2[mt][nt][q] = 0.0f;

    #pragma unroll
    for (int ks = 0; ks < HID / 16; ks++) {          // 16 k-steps
        uint32_t h[2][4];
        #pragma unroll
        for (int mt = 0; mt < 2; mt++)
            ldsm_x4(h[mt], Hs + (mrow + mt * 16 + lrow + (lsel & 1) * 8) * HS_LDW
                              + ks * 8 + (lsel >> 1) * 4);
        #pragma unroll
        for (int nt = 0; nt < 2; nt++) {
            int col = nb2 + nt * 8 + g;
            uint32_t b0 = Wp2s[col * W2_LDW + ks * 8 + t];
            uint32_t bv = Wp2s[col * W2_LDW + ks * 8 + t + 4];
            mma_bf16(acc2[0][nt], h[0], b0, bv);
            mma_bf16(acc2[1][nt], h[1], b0, bv);
        }
    }

    // epilogue 2: + b2 -> g_feature (guard tail rows)
    #pragma unroll
    for (int mt = 0; mt < 2; mt++) {
        #pragma unroll
        for (int nt = 0; nt < 2; nt++) {
            int r   = row0 + mrow + mt * 16 + g;
            int col = nb2 + nt * 8 + 2 * t;
            float2 lo = make_float2(acc2[mt][nt][0] + b2s[col],
                                    acc2[mt][nt][1] + b2s[col + 1]);
            float2 hi = make_float2(acc2[mt][nt][2] + b2s[col],
                                    acc2[mt][nt][3] + b2s[col + 1]);
            if (r < NUM_ITEM)
                *(float2*)(g_feature + (size_t)r * DIM_E + col) = lo;
            if (r + 8 < NUM_ITEM)
                *(float2*)(g_feature + (size_t)(r + 8) * DIM_E + col) = hi;
        }
    }
}

// ---------------------------------------------------------------------------
// Loss: one warp per batch row (17 pairs). Lanes cover 64 dims as float2.
// ---------------------------------------------------------------------------
__global__ void __launch_bounds__(256) loss_kernel(
    const float* __restrict__ id_emb,
    const int*   __restrict__ user_t,
    const int*   __restrict__ item_t)
{
    __shared__ float bs[2];
    if (threadIdx.x == 0) { bs[0] = 0.0f; bs[1] = 0.0f; }
    __syncthreads();

    int warp = (blockIdx.x * blockDim.x + threadIdx.x) >> 5;
    int lane = threadIdx.x & 31;

    if (warp < BATCH) {
        int base = warp * GRP;
        int pit  = item_t[base];
        float2 pe = ((const float2*)(id_emb + (size_t)pit * DIM_E))[lane];
        float ps = fmaf(pe.x, pe.x, pe.y * pe.y);
        #pragma unroll
        for (int o = 16; o; o >>= 1) ps += __shfl_xor_sync(0xffffffffu, ps, o);
        float inv_p = 1.0f / fmaxf(sqrtf(ps), 1e-12f);

        float tot1 = 0.0f, tot2 = 0.0f, pos1 = 0.0f, pos2 = 0.0f;
        #pragma unroll 4
        for (int gi = 0; gi < GRP; ++gi) {
            int it = item_t[base + gi];
            int u  = user_t[base + gi];
            int item = it - NUM_USER;
            item = min(max(item, 0), NUM_ITEM - 1);

            float2 f  = ((const float2*)(g_feature + (size_t)item * DIM_E))[lane];
            float2 ue = ((const float2*)(id_emb + (size_t)u * DIM_E))[lane];
            float2 av;
            if (g_mask[base + gi]) av = f;
            else av = ((const float2*)(id_emb + (size_t)it * DIM_E))[lane];

            float fn = fmaf(f.x, f.x, f.y * f.y);
            float d1 = fmaf(pe.x, f.x, pe.y * f.y);
            float d2 = fmaf(ue.x, av.x, ue.y * av.y);
            #pragma unroll
            for (int o = 16; o; o >>= 1) {
                fn += __shfl_xor_sync(0xffffffffu, fn, o);
                d1 += __shfl_xor_sync(0xffffffffu, d1, o);
                d2 += __shfl_xor_sync(0xffffffffu, d2, o);
            }
            float inv_f = 1.0f / fmaxf(sqrtf(fn), 1e-12f);
            float s1 = expf(d1 * inv_p * inv_f * 5.0f);
            float s2 = expf(d2 * 5.0f);
            tot1 += s1; tot2 += s2;
            if (gi == 0) { pos1 = s1; pos2 = s2; }
        }
        if (lane == 0) {
            atomicAdd(&bs[0], -logf(pos1 / (tot1 + 1e-8f) + 1e-8f));
            atomicAdd(&bs[1], -logf(pos2 / (tot2 + 1e-8f) + 1e-8f));
        }
    }
    __syncthreads();
    if (threadIdx.x == 0) {
        atomicAdd(&g_accum[0], bs[0]);
        atomicAdd(&g_accum[1], bs[1]);
    }
}

// ---------------------------------------------------------------------------
__global__ void finalize_kernel(float* __restrict__ out, int n) {
    float v = (g_accum[0] + g_accum[1]) * (0.5f / (float)BATCH);
    for (int i = threadIdx.x; i < n; i += blockDim.x) out[i] = v;
}

// ---------------------------------------------------------------------------
extern "C" void kernel_launch(void* const* d_in, const int* in_sizes, int n_in,
                              void* d_out, int out_size)
{
    const float* v_feat = (const float*)d_in[0];
    const float* id_emb = (const float*)d_in[1];
    const float* W1     = (const float*)d_in[2];
    const float* b1     = (const float*)d_in[3];
    const float* W2     = (const float*)d_in[4];
    const float* b2     = (const float*)d_in[5];
    const int*   user_t = (const int*)d_in[6];
    const int*   item_t = (const int*)d_in[7];
    const int*   rand_i = (const int*)d_in[8];
    const int    n_rand = in_sizes[8];
    float*       out    = (float*)d_out;

    const size_t smem = (size_t)SMEM_WORDS * 4;   // ~207 KB
    cudaFuncSetAttribute(encoder_kernel,
                         cudaFuncAttributeMaxDynamicSharedMemorySize, (int)smem);

    zero_kernel<<<(NTOT / 4 + 255) / 256, 256>>>();
    scatter_kernel<<<(n_rand + 255) / 256, 256>>>(rand_i, n_rand);
    pack_kernel<<<(WP1_WORDS + WP2_WORDS + 255) / 256, 256>>>(W1, W2);
    encoder_kernel<<<(NUM_ITEM + MTILE - 1) / MTILE, THREADS, smem>>>(v_feat, b1, b2);
    loss_kernel<<<BATCH / 8, 256>>>(id_emb, user_t, item_t);
    finalize_kernel<<<1, 32>>>(out, out_size > 0 ? out_size : 1);
}